// round 9
// baseline (speedup 1.0000x reference)
#include <cuda_runtime.h>
#include <cuda_fp16.h>

// ---------------------------------------------------------------------------
// VentralModel pooling, round 9: single persistent fused kernel.
//   Phase 1: all blocks compute moduli -> g_m (__half, 2.8 MB, L2-resident)
//   (grid barrier)
//   Phase 2: 3600 static round-robin chunk tasks (128 KB heavy chunks)
//   (grid barrier)
//   Phase 3: finalize -> out
// grid=296 (= 2 blocks/SM, co-resident by __launch_bounds__(512,2)), so the
// software grid barriers cannot deadlock. Barrier counters self-reset, safe
// across graph replays. Results are deterministic (static task map; atomics
// only control the barrier).
// Output: [s*1200 + o*300 + w] s=0..3, then [4800 + w] mean luminance.
// ---------------------------------------------------------------------------

#define NBLK 296
#define NTHR 512

// modulus scratch (half): s0 @0 (4*262144), s1 @1048576 (4*65536),
// s2 @1310720 (4*16384), s3 @1376256 (4*4096)
static __device__ __half g_m[1392640];
// per-task partials: [task*8 + {a0,a1,a2,a3,aL,cf}]
static __device__ float g_part[3600 * 8];
// grid-barrier state (zero-initialized; self-resetting each call)
static __device__ unsigned int b_arr[2];
static __device__ unsigned int b_done[2];

static __device__ __forceinline__ void grid_bar(int id)
{
    __syncthreads();
    if (threadIdx.x == 0) {
        __threadfence();                       // publish this block's writes
        atomicAdd(&b_arr[id], 1u);
        volatile unsigned int* p = &b_arr[id];
        while (*p < (unsigned)NBLK) {}
        __threadfence();                       // acquire others' writes
        unsigned int d = atomicAdd(&b_done[id], 1u);
        if (d == (unsigned)(NBLK - 1)) {       // last one out resets
            b_arr[id] = 0u;
            __threadfence();
            b_done[id] = 0u;
        }
    }
    __syncthreads();
}

static __device__ __forceinline__ float warp_red(float v) {
    #pragma unroll
    for (int o = 16; o > 0; o >>= 1)
        v += __shfl_down_sync(0xffffffffu, v, o);
    return v;
}

// Dot of fp32 window group (4 px) with 4 fp16 moduli loaded as one LDG.64.
static __device__ __forceinline__ float dot_h4(const uint2* base, int idx,
                                               float4 q)
{
    uint2 u = __ldg(base + idx);
    __half2 h0 = *(__half2*)&u.x;
    __half2 h1 = *(__half2*)&u.y;
    float2 f0 = __half22float2(h0);
    float2 f1 = __half22float2(h1);
    return q.x * f0.x + q.y * f0.y + q.z * f1.x + q.w * f1.y;
}

// Window values are non-negative; sum==0 <=> all four are zero.
#define GROUP(Q, IDX)                                                          \
    do {                                                                       \
        float4 q_ = (Q); int i_ = (IDX);                                       \
        float s_ = (q_.x + q_.y) + (q_.z + q_.w);                              \
        if (s_ > 0.f) {                                                        \
            cf += (q_.x > 0.f ? 1.f : 0.f) + (q_.y > 0.f ? 1.f : 0.f)          \
                + (q_.z > 0.f ? 1.f : 0.f) + (q_.w > 0.f ? 1.f : 0.f);         \
            a0 += dot_h4(m0, i_, q_);                                          \
            a1 += dot_h4(m1, i_, q_);                                          \
            a2 += dot_h4(m2, i_, q_);                                          \
            a3 += dot_h4(m3, i_, q_);                                          \
            if (do_img) {                                                      \
                float4 v_ = iv[i_];                                            \
                aL += q_.x*v_.x + q_.y*v_.y + q_.z*v_.z + q_.w*v_.w;           \
            }                                                                  \
        }                                                                      \
    } while (0)

// Task map (3600 tasks, static round-robin over 296 blocks):
//  [0,2400)    scale0: w=t>>3, q=t&7, nv=8192 float4 (128 KB)
//  [2400,3000) scale1: w=(t-2400)>>1, q=(t-2400)&1, nv=8192 (128 KB)
//  [3000,3300) scale2: nv=4096 (64 KB)
//  [3300,3600) scale3: nv=1024 (16 KB)
__global__ __launch_bounds__(NTHR, 2) void fused_kernel(
    const float* __restrict__ p0, const float* __restrict__ p1,
    const float* __restrict__ p2, const float* __restrict__ p3,
    const float* __restrict__ w0, const float* __restrict__ w1,
    const float* __restrict__ w2, const float* __restrict__ w3,
    const float* __restrict__ img, float* __restrict__ out)
{
    __shared__ float sm[16][6];

    // ---------------- Phase 1: moduli (full chip) ----------------
    {
        int gt = blockIdx.x * NTHR + threadIdx.x;     // 0..151551
        for (int i = gt; i < 696320; i += NBLK * NTHR) {
            int pi = i * 2;                           // pair (modulus) index
            const float4* p;
            int off;
            if (pi < 1048576)      { p = (const float4*)p0; off = i; }
            else if (pi < 1310720) { p = (const float4*)p1; off = i - (1048576 >> 1); }
            else if (pi < 1376256) { p = (const float4*)p2; off = i - (1310720 >> 1); }
            else                   { p = (const float4*)p3; off = i - (1376256 >> 1); }
            float4 v = p[off];
            float rx = sqrtf(v.x * v.x + v.y * v.y);
            float ry = sqrtf(v.z * v.z + v.w * v.w);
            ((__half2*)g_m)[i] = __floats2half2_rn(rx, ry);
        }
    }
    grid_bar(0);

    // ---------------- Phase 2: pooling tasks ----------------
    for (int t = blockIdx.x; t < 3600; t += NBLK) {
        const float* winp; const __half* mh;
        int n, nv_c, cw_off, m_off;
        bool do_img = false;

        if (t < 2400) {
            int w = t >> 3, q = t & 7;
            winp = w0; mh = g_m; n = 262144;
            nv_c = 8192; cw_off = w * 65536 + q * 8192; m_off = q * 8192;
            do_img = true;
        } else if (t < 3000) {
            int u = t - 2400, w = u >> 1, q = u & 1;
            winp = w1; mh = g_m + 1048576; n = 65536;
            nv_c = 8192; cw_off = w * 16384 + q * 8192; m_off = q * 8192;
        } else if (t < 3300) {
            int w = t - 3000;
            winp = w2; mh = g_m + 1310720; n = 16384;
            nv_c = 4096; cw_off = w * 4096; m_off = 0;
        } else {
            int w = t - 3300;
            winp = w3; mh = g_m + 1376256; n = 4096;
            nv_c = 1024; cw_off = w * 1024; m_off = 0;
        }

        const float4* wv = (const float4*)winp + cw_off;
        const uint2* m0 = (const uint2*)mh + m_off;
        const uint2* m1 = (const uint2*)(mh + n) + m_off;
        const uint2* m2 = (const uint2*)(mh + 2 * n) + m_off;
        const uint2* m3 = (const uint2*)(mh + 3 * n) + m_off;
        const float4* iv = (const float4*)img + m_off;

        float a0 = 0.f, a1 = 0.f, a2 = 0.f, a3 = 0.f, aL = 0.f, cf = 0.f;

        if (nv_c >= 2048) {
            // unroll x4, no guards (nv_c % 2048 == 0)
            for (int i = threadIdx.x; i < nv_c; i += 2048) {
                float4 q0 = __ldcs(wv + i);
                float4 q1 = __ldcs(wv + i + 512);
                float4 q2 = __ldcs(wv + i + 1024);
                float4 q3 = __ldcs(wv + i + 1536);
                GROUP(q0, i);
                GROUP(q1, i + 512);
                GROUP(q2, i + 1024);
                GROUP(q3, i + 1536);
            }
        } else {
            for (int i = threadIdx.x; i < nv_c; i += 512) {
                float4 q0 = __ldcs(wv + i);
                GROUP(q0, i);
            }
        }

        // block reduction (16 warps)
        int lane = threadIdx.x & 31, wid = threadIdx.x >> 5;
        a0 = warp_red(a0); a1 = warp_red(a1); a2 = warp_red(a2);
        a3 = warp_red(a3); aL = warp_red(aL); cf = warp_red(cf);
        if (lane == 0) {
            sm[wid][0] = a0; sm[wid][1] = a1; sm[wid][2] = a2;
            sm[wid][3] = a3; sm[wid][4] = aL; sm[wid][5] = cf;
        }
        __syncthreads();
        if (threadIdx.x < 6) {
            float r = 0.f;
            #pragma unroll
            for (int k = 0; k < 16; k++) r += sm[k][threadIdx.x];
            g_part[t * 8 + threadIdx.x] = r;
        }
        __syncthreads();   // sm reused next task
    }
    grid_bar(1);

    // ---------------- Phase 3: finalize ----------------
    {
        int o = blockIdx.x * NTHR + threadIdx.x;
        if (o < 1200) {
            int sc = o / 300, w = o % 300;
            float s0 = 0.f, s1 = 0.f, s2 = 0.f, s3 = 0.f, sL = 0.f, cnt = 0.f;
            if (sc == 0) {
                #pragma unroll
                for (int q = 0; q < 8; q++) {
                    const float* p = g_part + (w * 8 + q) * 8;
                    s0 += p[0]; s1 += p[1]; s2 += p[2];
                    s3 += p[3]; sL += p[4]; cnt += p[5];
                }
            } else if (sc == 1) {
                #pragma unroll
                for (int q = 0; q < 2; q++) {
                    const float* p = g_part + (2400 + w * 2 + q) * 8;
                    s0 += p[0]; s1 += p[1]; s2 += p[2];
                    s3 += p[3]; sL += p[4]; cnt += p[5];
                }
            } else {
                const float* p = g_part + (2400 + sc * 300 + w) * 8;  // sc2->3000+w, sc3->3300+w
                s0 = p[0]; s1 = p[1]; s2 = p[2]; s3 = p[3]; sL = p[4]; cnt = p[5];
            }
            float inv = 1.f / cnt;
            int ob = sc * 1200;
            out[ob + 0 * 300 + w] = s0 * inv;
            out[ob + 1 * 300 + w] = s1 * inv;
            out[ob + 2 * 300 + w] = s2 * inv;
            out[ob + 3 * 300 + w] = s3 * inv;
            if (sc == 0) out[4800 + w] = sL * inv;
        }
    }
}

extern "C" void kernel_launch(void* const* d_in, const int* in_sizes, int n_in,
                              void* d_out, int out_size)
{
    const float *img = nullptr, *p0 = nullptr, *p1 = nullptr, *p2 = nullptr, *p3 = nullptr;
    const float *w0 = nullptr, *w1 = nullptr, *w2 = nullptr, *w3 = nullptr;

    for (int i = 0; i < n_in; i++) {
        switch (in_sizes[i]) {
            case 262144:   img = (const float*)d_in[i]; break;   // image 512^2
            case 2097152:  p0  = (const float*)d_in[i]; break;   // pyr0
            case 78643200: w0  = (const float*)d_in[i]; break;   // win0
            case 524288:   p1  = (const float*)d_in[i]; break;   // pyr1
            case 19660800: w1  = (const float*)d_in[i]; break;   // win1
            case 131072:   p2  = (const float*)d_in[i]; break;   // pyr2
            case 4915200:  w2  = (const float*)d_in[i]; break;   // win2
            case 32768:    p3  = (const float*)d_in[i]; break;   // pyr3
            case 1228800:  w3  = (const float*)d_in[i]; break;   // win3
        }
    }

    fused_kernel<<<NBLK, NTHR>>>(p0, p1, p2, p3, w0, w1, w2, w3, img,
                                 (float*)d_out);
}

// round 10
// speedup vs baseline: 1.2613x; 1.2613x over previous
#include <cuda_runtime.h>
#include <cuda_fp16.h>

// ---------------------------------------------------------------------------
// VentralModel pooling, round 10: R7 structure (best known) + finalize fused
// into the last-finishing pool block (saves a kernel launch + ~2 us).
//   modulus_kernel : m = sqrt(re^2+im^2) -> g_m as __half (2.8 MB, L2-res)
//   pool_kernel    : 2100 chunk-tasks x 512 thr; partials -> g_part;
//                    last block (completion counter) finalizes -> out
// Output: [s*1200 + o*300 + w] s=0..3, then [4800 + w] mean luminance.
// ---------------------------------------------------------------------------

// modulus scratch (half): s0 @0 (4*262144), s1 @1048576 (4*65536),
// s2 @1310720 (4*16384), s3 @1376256 (4*4096)
static __device__ __half g_m[1392640];
// per-task partials: [task*8 + {a0,a1,a2,a3,aL,cf}]
static __device__ float g_part[2100 * 8];
// completed-task counter (zero-init; reset by the finalizing block each call)
static __device__ unsigned int g_done;

__global__ __launch_bounds__(256) void modulus_kernel(
    const float* __restrict__ p0, const float* __restrict__ p1,
    const float* __restrict__ p2, const float* __restrict__ p3)
{
    int i = blockIdx.x * blockDim.x + threadIdx.x;   // 696320 threads total
    int pi = i * 2;                                  // pair (modulus) index
    const float4* p;
    int off;
    if (pi < 1048576)      { p = (const float4*)p0; off = i; }
    else if (pi < 1310720) { p = (const float4*)p1; off = i - (1048576 >> 1); }
    else if (pi < 1376256) { p = (const float4*)p2; off = i - (1310720 >> 1); }
    else                   { p = (const float4*)p3; off = i - (1376256 >> 1); }
    float4 v = p[off];
    float rx = sqrtf(v.x * v.x + v.y * v.y);
    float ry = sqrtf(v.z * v.z + v.w * v.w);
    ((__half2*)g_m)[i] = __floats2half2_rn(rx, ry);
}

static __device__ __forceinline__ float warp_red(float v) {
    #pragma unroll
    for (int o = 16; o > 0; o >>= 1)
        v += __shfl_down_sync(0xffffffffu, v, o);
    return v;
}

// Dot of fp32 window group (4 px) with 4 fp16 moduli loaded as one LDG.64.
static __device__ __forceinline__ float dot_h4(const uint2* base, int idx,
                                               float4 q)
{
    uint2 u = __ldg(base + idx);
    __half2 h0 = *(__half2*)&u.x;
    __half2 h1 = *(__half2*)&u.y;
    float2 f0 = __half22float2(h0);
    float2 f1 = __half22float2(h1);
    return q.x * f0.x + q.y * f0.y + q.z * f1.x + q.w * f1.y;
}

// Window values are non-negative; sum==0 <=> all four are zero.
#define GROUP(Q, IDX)                                                          \
    do {                                                                       \
        float4 q_ = (Q); int i_ = (IDX);                                       \
        float s_ = (q_.x + q_.y) + (q_.z + q_.w);                              \
        if (s_ > 0.f) {                                                        \
            cf += (q_.x > 0.f ? 1.f : 0.f) + (q_.y > 0.f ? 1.f : 0.f)          \
                + (q_.z > 0.f ? 1.f : 0.f) + (q_.w > 0.f ? 1.f : 0.f);         \
            a0 += dot_h4(m0, i_, q_);                                          \
            a1 += dot_h4(m1, i_, q_);                                          \
            a2 += dot_h4(m2, i_, q_);                                          \
            a3 += dot_h4(m3, i_, q_);                                          \
            if (do_img) {                                                      \
                float4 v_ = iv[i_];                                            \
                aL += q_.x*v_.x + q_.y*v_.y + q_.z*v_.z + q_.w*v_.w;           \
            }                                                                  \
        }                                                                      \
    } while (0)

// Task map (2100 blocks of 512 threads):
//  [0,1200)    scale0: w=t>>2, q=t&3, nv=16384 float4 (256 KB)
//  [1200,1500) scale1: nv=16384 (256 KB)
//  [1500,1800) scale2: nv=4096  (64 KB)
//  [1800,2100) scale3: nv=1024  (16 KB)
__global__ __launch_bounds__(512) void pool_kernel(
    const float* __restrict__ w0, const float* __restrict__ w1,
    const float* __restrict__ w2, const float* __restrict__ w3,
    const float* __restrict__ img, float* __restrict__ out)
{
    int t = blockIdx.x;
    const float* winp; const __half* mh;
    int n, nv_c, cw_off, m_off;
    bool do_img = false;

    if (t < 1200) {
        int w = t >> 2, q = t & 3;
        winp = w0; mh = g_m; n = 262144;
        nv_c = 16384; cw_off = w * 65536 + q * 16384; m_off = q * 16384;
        do_img = true;
    } else if (t < 1500) {
        int w = t - 1200;
        winp = w1; mh = g_m + 1048576; n = 65536;
        nv_c = 16384; cw_off = w * 16384; m_off = 0;
    } else if (t < 1800) {
        int w = t - 1500;
        winp = w2; mh = g_m + 1310720; n = 16384;
        nv_c = 4096; cw_off = w * 4096; m_off = 0;
    } else {
        int w = t - 1800;
        winp = w3; mh = g_m + 1376256; n = 4096;
        nv_c = 1024; cw_off = w * 1024; m_off = 0;
    }

    const float4* wv = (const float4*)winp + cw_off;
    const uint2* m0 = (const uint2*)mh + m_off;
    const uint2* m1 = (const uint2*)(mh + n) + m_off;
    const uint2* m2 = (const uint2*)(mh + 2 * n) + m_off;
    const uint2* m3 = (const uint2*)(mh + 3 * n) + m_off;
    const float4* iv = (const float4*)img + m_off;

    float a0 = 0.f, a1 = 0.f, a2 = 0.f, a3 = 0.f, aL = 0.f, cf = 0.f;

    if (nv_c >= 2048) {
        // unroll x4, no guards (nv_c % 2048 == 0): 4 window loads in flight
        for (int i = threadIdx.x; i < nv_c; i += 2048) {
            float4 q0 = __ldcs(wv + i);
            float4 q1 = __ldcs(wv + i + 512);
            float4 q2 = __ldcs(wv + i + 1024);
            float4 q3 = __ldcs(wv + i + 1536);
            GROUP(q0, i);
            GROUP(q1, i + 512);
            GROUP(q2, i + 1024);
            GROUP(q3, i + 1536);
        }
    } else {
        for (int i = threadIdx.x; i < nv_c; i += 512) {
            float4 q0 = __ldcs(wv + i);
            GROUP(q0, i);
        }
    }

    // block reduction (16 warps)
    __shared__ float sm[16][6];
    __shared__ int s_last;
    int lane = threadIdx.x & 31, wid = threadIdx.x >> 5;
    a0 = warp_red(a0); a1 = warp_red(a1); a2 = warp_red(a2);
    a3 = warp_red(a3); aL = warp_red(aL); cf = warp_red(cf);
    if (lane == 0) {
        sm[wid][0] = a0; sm[wid][1] = a1; sm[wid][2] = a2;
        sm[wid][3] = a3; sm[wid][4] = aL; sm[wid][5] = cf;
    }
    __syncthreads();
    if (threadIdx.x < 6) {
        float r = 0.f;
        #pragma unroll
        for (int k = 0; k < 16; k++) r += sm[k][threadIdx.x];
        g_part[t * 8 + threadIdx.x] = r;
    }
    __syncthreads();

    // completion protocol: last block to finish runs finalize inline
    if (threadIdx.x == 0) {
        __threadfence();                                  // publish g_part[t]
        unsigned int d = atomicAdd(&g_done, 1u);
        s_last = (d == 2099u) ? 1 : 0;
    }
    __syncthreads();
    if (!s_last) return;

    __threadfence();                                      // acquire all g_part
    for (int o = threadIdx.x; o < 1200; o += 512) {
        int sc = o / 300, w = o % 300;
        float s0 = 0.f, s1 = 0.f, s2 = 0.f, s3 = 0.f, sL = 0.f, cnt = 0.f;
        if (sc == 0) {
            #pragma unroll
            for (int q = 0; q < 4; q++) {
                const float* p = g_part + (w * 4 + q) * 8;
                s0 += p[0]; s1 += p[1]; s2 += p[2];
                s3 += p[3]; sL += p[4]; cnt += p[5];
            }
        } else {
            const float* p = g_part + (900 + sc * 300 + w) * 8;  // sc1->1200+w, ...
            s0 = p[0]; s1 = p[1]; s2 = p[2]; s3 = p[3]; sL = p[4]; cnt = p[5];
        }
        float inv = 1.f / cnt;
        int ob = sc * 1200;
        out[ob + 0 * 300 + w] = s0 * inv;
        out[ob + 1 * 300 + w] = s1 * inv;
        out[ob + 2 * 300 + w] = s2 * inv;
        out[ob + 3 * 300 + w] = s3 * inv;
        if (sc == 0) out[4800 + w] = sL * inv;
    }
    __syncthreads();
    if (threadIdx.x == 0) g_done = 0u;                    // reset for next replay
}

extern "C" void kernel_launch(void* const* d_in, const int* in_sizes, int n_in,
                              void* d_out, int out_size)
{
    const float *img = nullptr, *p0 = nullptr, *p1 = nullptr, *p2 = nullptr, *p3 = nullptr;
    const float *w0 = nullptr, *w1 = nullptr, *w2 = nullptr, *w3 = nullptr;

    for (int i = 0; i < n_in; i++) {
        switch (in_sizes[i]) {
            case 262144:   img = (const float*)d_in[i]; break;   // image 512^2
            case 2097152:  p0  = (const float*)d_in[i]; break;   // pyr0
            case 78643200: w0  = (const float*)d_in[i]; break;   // win0
            case 524288:   p1  = (const float*)d_in[i]; break;   // pyr1
            case 19660800: w1  = (const float*)d_in[i]; break;   // win1
            case 131072:   p2  = (const float*)d_in[i]; break;   // pyr2
            case 4915200:  w2  = (const float*)d_in[i]; break;   // win2
            case 32768:    p3  = (const float*)d_in[i]; break;   // pyr3
            case 1228800:  w3  = (const float*)d_in[i]; break;   // win3
        }
    }

    modulus_kernel<<<2720, 256>>>(p0, p1, p2, p3);   // 696320 threads
    pool_kernel<<<2100, 512>>>(w0, w1, w2, w3, img, (float*)d_out);
}